// round 16
// baseline (speedup 1.0000x reference)
#include <cuda_runtime.h>
#include <cuda_bf16.h>
#include <cstdint>

// Problem constants
#define KN 4096      // nodes
#define KF 32        // features
#define KHF 64       // heads*features
#define KNHID 64
#define KC 10
#define KE 65536     // edges
#define KG 13        // branches
#define KNN (KN*KN)
#define KNF (KN*KF)
#define GCAP 192     // max cached degree per dst

// ---------------- device scratch (no allocations allowed) ----------------
__device__ __align__(128) __nv_bfloat16 g_Bh[KG * KF * KN]; // B operands [slot][f][node]
__device__ __align__(128) __nv_bfloat16 g_Bl[KG * KF * KN];
__device__ __align__(128) __nv_bfloat16 g_Uh[KNN];          // U bf16 hi
__device__ __align__(128) __nv_bfloat16 g_Ul[KNN];          // U bf16 lo
__device__ float g_part[39ull * KN * KF]; // split-K partials (max: mode2 3x13)
__device__ float g_h[KG * KN * KHF];     // per-branch GAT hidden [13][N][64]
__device__ float g_es[KG * KN * 2];
__device__ float g_ed[KG * KN * 2];
__device__ float g_feat[KN * KG * KNHID];// [N][832]
__device__ int   g_deg[KN];
__device__ int   g_rowptr[KN + 1];
__device__ int   g_pos[KN];
__device__ int   g_srcs[KE + KN];

// ---------------- helpers ----------------
__device__ __forceinline__ float lrelu(float v) { return v > 0.f ? v : 0.2f * v; }
__device__ __forceinline__ float eluf(float v)  { return v > 0.f ? v : expm1f(v); }

__device__ __forceinline__ uint32_t su32(const void* p) {
    return (uint32_t)__cvta_generic_to_shared(p);
}
__device__ __forceinline__ void cpa16(uint32_t dst, const void* src) {
    asm volatile("cp.async.cg.shared.global [%0], [%1], 16;" :: "r"(dst), "l"(src) : "memory");
}
__device__ __forceinline__ uint32_t swz64(uint32_t off) { return off ^ ((off >> 3) & 0x30); }

#define LDSM4(d, addr) \
    asm volatile("ldmatrix.sync.aligned.m8n8.x4.shared.b16 {%0,%1,%2,%3}, [%4];" \
        : "=r"((d)[0]), "=r"((d)[1]), "=r"((d)[2]), "=r"((d)[3]) : "r"(addr))

__device__ __forceinline__ void mma_bf16(float* c, const uint32_t* a,
                                         uint32_t b0, uint32_t b1) {
    asm volatile("mma.sync.aligned.m16n8k16.row.col.f32.bf16.bf16.f32 "
        "{%0,%1,%2,%3}, {%4,%5,%6,%7}, {%8,%9}, {%0,%1,%2,%3};"
        : "+f"(c[0]), "+f"(c[1]), "+f"(c[2]), "+f"(c[3])
        : "r"(a[0]), "r"(a[1]), "r"(a[2]), "r"(a[3]), "r"(b0), "r"(b1));
}

__device__ __forceinline__ uint32_t pack_bf16(__nv_bfloat16 a, __nv_bfloat16 b) {
    __nv_bfloat162 t(a, b);
    return *(uint32_t*)&t;
}

// ---------------- |x| -> transposed bf16 split (B slot 0) ----------------
__global__ __launch_bounds__(256) void k_absT2(const float* __restrict__ x) {
    __shared__ float T[32 * 129];
    int nodeBase = blockIdx.x * 128;
    int t = threadIdx.x;
    const float* src = x + (size_t)nodeBase * 32;
    for (int i = t; i < 4096; i += 256) {
        int node = i >> 5, f = i & 31;
        T[f * 129 + node] = fabsf(src[i]);
    }
    __syncthreads();
    for (int i = t; i < 4096; i += 256) {
        int f = i >> 7, node = i & 127;
        float v = T[f * 129 + node];
        __nv_bfloat16 h = __float2bfloat16(v);
        size_t o = (size_t)f * KN + nodeBase + node;
        g_Bh[o] = h;
        g_Bl[o] = __float2bfloat16(v - __bfloat162float(h));
    }
}

// ---------------- U fp32 -> bf16 hi/lo (elementwise, coalesced) ----------------
__global__ __launch_bounds__(256) void k_convU(const float* __restrict__ U) {
    size_t i = ((size_t)blockIdx.x * 256 + threadIdx.x) * 4;
    if (i >= (size_t)KNN) return;
    float4 v = *(const float4*)(U + i);
    __nv_bfloat16 h0 = __float2bfloat16(v.x), h1 = __float2bfloat16(v.y);
    __nv_bfloat16 h2 = __float2bfloat16(v.z), h3 = __float2bfloat16(v.w);
    *(uint2*)(g_Uh + i) = make_uint2(pack_bf16(h0, h1), pack_bf16(h2, h3));
    *(uint2*)(g_Ul + i) = make_uint2(
        pack_bf16(__float2bfloat16(v.x - __bfloat162float(h0)),
                  __float2bfloat16(v.y - __bfloat162float(h1))),
        pack_bf16(__float2bfloat16(v.z - __bfloat162float(h2)),
                  __float2bfloat16(v.w - __bfloat162float(h3))));
}

// ---------------- split-K reduce + abs + bf16-split, 64-node tiles ----------
__global__ __launch_bounds__(256) void k_redT(int stride, int outBase) {
    __shared__ float T[32 * 65];
    int lin = blockIdx.y;
    int nodeBase = blockIdx.x * 64;
    int t = threadIdx.x;
    const float* p0 = g_part + (size_t)lin * KNF + (size_t)nodeBase * 32;
    for (int i = t; i < 2048; i += 256) {
        int node = i >> 5, f = i & 31;
        T[f * 65 + node] = fabsf(p0[i] + p0[i + (size_t)stride] + p0[i + 2 * (size_t)stride]);
    }
    __syncthreads();
    for (int i = t; i < 2048; i += 256) {
        int f = i >> 6, node = i & 63;
        float v = T[f * 65 + node];
        __nv_bfloat16 h = __float2bfloat16(v);
        size_t o = (size_t)(outBase + lin) * KNF + (size_t)f * KN + nodeBase + node;
        g_Bh[o] = h;
        g_Bl[o] = __float2bfloat16(v - __bfloat162float(h));
    }
}

// ---------------- mma.sync scattering GEMM ----------------
// mode 0 (NB1,PREF):  A=psi_y fp32 inline-split, in slot0,  partial z*3+y.  (32,3,3)
// mode 1 (NB3,PREF):  A=psi_y fp32 inline-split, in {1,2,3}, partial z*9+3b+y. (32,3,3)
// mode 2 (NB4,AEXT):  A=g_Uh/g_Ul cp.async, in {4y+b}, y=blockIdx.y+ybase.
// mode 2 (NB1,AEXT):  A=g_Uh/g_Ul cp.async, in {12}.
template <int NB, bool PREF, bool AEXT>
__global__ __launch_bounds__(256, 2) void k_mma(int mode, const float* __restrict__ U,
                                                const float* __restrict__ psi, int ybase) {
    extern __shared__ char dsm[];
    int tid = threadIdx.x;
    uint32_t sraw = su32(dsm);
    uint32_t sbase = (sraw + 1023u) & ~1023u;
    char* smp = dsm + (sbase - sraw);          // generic pointer to aligned base

    int y = blockIdx.y + ybase;
    int z = blockIdx.z;
    int rowBase = blockIdx.x * 128;
    int slotIn[NB], rawIdx[NB];
    const float* Afp = nullptr;
    int cBeg = (z * 128) / 3, cEnd = ((z + 1) * 128) / 3;   // chunk32 indices
    if (mode == 0) {
        Afp = psi + (size_t)y * KNN;
        slotIn[0] = 0; rawIdx[0] = z * 3 + y;
    } else if (mode == 1) {
        Afp = psi + (size_t)y * KNN;
        #pragma unroll
        for (int b = 0; b < NB; b++) { slotIn[b] = 1 + b; rawIdx[b] = z * 9 + 3 * b + y; }
    } else {
        #pragma unroll
        for (int b = 0; b < NB; b++) {
            int s = (NB == 1) ? 12 : (4 * y + b);
            slotIn[b] = s; rawIdx[b] = z * 13 + s;
        }
    }

    constexpr uint32_t ABytes = AEXT ? 49152u : 32768u;
    auto A_at = [&](int st, int p) { return sbase + (uint32_t)(st * 2 + p) * 8192u; };
    auto A_off = [&](int st, int p) { return (uint32_t)(st * 2 + p) * 8192u; };
    auto B_at = [&](int st, int p, int b) {
        return sbase + ABytes + (uint32_t)((st * 2 + p) * NB + b) * 2048u;
    };

    float buf[PREF ? 16 : (AEXT ? 1 : 16)];
    auto ldgA = [&](int c) {
        if (AEXT) return;
        #pragma unroll
        for (int it = 0; it < 4; it++) {
            int i = it * 256 + tid;
            int r = i >> 3, seg = i & 7;
            *(float4*)(buf + it * 4) =
                *(const float4*)(Afp + (size_t)(rowBase + r) * KN + c * 32 + seg * 4);
        }
    };
    auto stsA = [&](int st) {
        if (AEXT) return;
        #pragma unroll
        for (int it = 0; it < 4; it++) {
            int i = it * 256 + tid;
            int r = i >> 3, seg = i & 7;
            float v0 = buf[it * 4 + 0], v1 = buf[it * 4 + 1];
            float v2 = buf[it * 4 + 2], v3 = buf[it * 4 + 3];
            __nv_bfloat16 h0 = __float2bfloat16(v0), h1 = __float2bfloat16(v1);
            __nv_bfloat16 h2 = __float2bfloat16(v2), h3 = __float2bfloat16(v3);
            uint2 hi = make_uint2(pack_bf16(h0, h1), pack_bf16(h2, h3));
            uint2 lo = make_uint2(
                pack_bf16(__float2bfloat16(v0 - __bfloat162float(h0)),
                          __float2bfloat16(v1 - __bfloat162float(h1))),
                pack_bf16(__float2bfloat16(v2 - __bfloat162float(h2)),
                          __float2bfloat16(v3 - __bfloat162float(h3))));
            uint32_t off = swz64((uint32_t)(r * 64 + seg * 8));
            *(uint2*)(smp + A_off(st, 0) + off) = hi;
            *(uint2*)(smp + A_off(st, 1) + off) = lo;
        }
    };
    auto ldAext = [&](int c, int s) {     // AEXT: A via cp.async from g_Uh/g_Ul
        int k0 = c * 32;
        #pragma unroll
        for (int it = 0; it < 2; it++) {
            int i = it * 256 + tid;       // 512 16B segs per part
            int r = i >> 2, seg = i & 3;
            uint32_t sw = swz64((uint32_t)(r * 64 + seg * 16));
            size_t go = (size_t)(rowBase + r) * KN + k0 + seg * 8;
            cpa16(A_at(s, 0) + sw, g_Uh + go);
            cpa16(A_at(s, 1) + sw, g_Ul + go);
        }
    };

    auto ldB = [&](int c, int s) {
        int k0 = c * 32;
        if (tid < 128) {
            int r = tid >> 2, seg = tid & 3;
            uint32_t sw = swz64((uint32_t)(r * 64 + seg * 16));
            #pragma unroll
            for (int b = 0; b < NB; b++) {
                size_t go = (size_t)slotIn[b] * (KF * KN) + (size_t)r * KN + k0 + seg * 8;
                cpa16(B_at(s, 0, b) + sw, g_Bh + go);
                cpa16(B_at(s, 1, b) + sw, g_Bl + go);
            }
        }
    };

    int wid = tid >> 5, lane = tid & 31;
    int wm = wid >> 1, wn = wid & 1;       // 4 M-warps x 2 N-warps

    auto aAddr = [&](uint32_t base, int mt, int q) {
        int row = wm * 32 + mt * 16 + (lane & 15);
        int colb = q * 32 + ((lane >> 4) << 4);
        return base + swz64((uint32_t)(row * 64 + colb));
    };
    auto bAddr = [&](uint32_t base, int n0, int q) {
        int j = lane >> 3, r = lane & 7;
        int row = n0 + ((j >> 1) << 3) + r;
        int colb = q * 32 + ((j & 1) << 4);
        return base + swz64((uint32_t)(row * 64 + colb));
    };

    float acc[2][2 * NB][4];
    #pragma unroll
    for (int mt = 0; mt < 2; mt++)
        #pragma unroll
        for (int n = 0; n < 2 * NB; n++)
            #pragma unroll
            for (int e = 0; e < 4; e++) acc[mt][n][e] = 0.f;

    // prologue
    if (AEXT) {
        ldAext(cBeg, 0);
        ldB(cBeg, 0);
        asm volatile("cp.async.commit_group;" ::: "memory");
        if (cBeg + 1 < cEnd) { ldAext(cBeg + 1, 1); ldB(cBeg + 1, 1); }
        asm volatile("cp.async.commit_group;" ::: "memory");
    } else {
        if (PREF) {
            ldgA(cBeg);
            stsA(0);
            if (cBeg + 1 < cEnd) ldgA(cBeg + 1);
        }
        ldB(cBeg, 0);
        asm volatile("cp.async.commit_group;" ::: "memory");
        if (cBeg + 1 < cEnd) ldB(cBeg + 1, 1);
        asm volatile("cp.async.commit_group;" ::: "memory");
        if (!PREF) {
            ldgA(cBeg);
            stsA(0);
        }
    }

    for (int i = cBeg; i < cEnd; i++) {
        int sA = AEXT ? ((i - cBeg) % 3) : ((i - cBeg) & 1);
        int sB = (i - cBeg) % 3;
        asm volatile("cp.async.wait_group 1;" ::: "memory");
        __syncthreads();
        if (i + 2 < cEnd) {
            if (AEXT) ldAext(i + 2, (i - cBeg + 2) % 3);
            ldB(i + 2, (i - cBeg + 2) % 3);
        }
        asm volatile("cp.async.commit_group;" ::: "memory");
        if (!AEXT) {
            if (PREF) {
                if (i + 1 < cEnd) {
                    stsA(sA ^ 1);
                    if (i + 2 < cEnd) ldgA(i + 2);
                }
            } else {
                if (i + 1 < cEnd) {
                    ldgA(i + 1);
                    stsA(sA ^ 1);
                }
            }
        }

        #pragma unroll
        for (int q = 0; q < 2; q++) {
            uint32_t ah[2][4], al[2][4];
            #pragma unroll
            for (int mt = 0; mt < 2; mt++) {
                LDSM4(ah[mt], aAddr(A_at(sA, 0), mt, q));
                LDSM4(al[mt], aAddr(A_at(sA, 1), mt, q));
            }
            #pragma unroll
            for (int t16 = 0; t16 < NB; t16++) {
                int g16 = wn * NB + t16;
                int b = g16 >> 1, n0 = (g16 & 1) * 16;
                uint32_t bh[4], bl[4];
                LDSM4(bh, bAddr(B_at(sB, 0, b), n0, q));
                LDSM4(bl, bAddr(B_at(sB, 1, b), n0, q));
                #pragma unroll
                for (int n8 = 0; n8 < 2; n8++) {
                    uint32_t h0 = bh[2 * n8], h1 = bh[2 * n8 + 1];
                    uint32_t l0 = bl[2 * n8], l1 = bl[2 * n8 + 1];
                    #pragma unroll
                    for (int mt = 0; mt < 2; mt++) {
                        float* c = acc[mt][t16 * 2 + n8];
                        mma_bf16(c, ah[mt], h0, h1);
                        mma_bf16(c, ah[mt], l0, l1);
                        mma_bf16(c, al[mt], h0, h1);
                    }
                }
            }
        }
    }

    // epilogue: raw fp32 partial stores
    int quad = lane >> 2, tq = lane & 3;
    #pragma unroll
    for (int mt = 0; mt < 2; mt++) {
        int rBase = rowBase + wm * 32 + mt * 16 + quad;
        #pragma unroll
        for (int t16 = 0; t16 < NB; t16++) {
            int g16 = wn * NB + t16;
            int b = g16 >> 1;
            float* ro = g_part + (size_t)rawIdx[b] * (KN * KF);
            #pragma unroll
            for (int n8 = 0; n8 < 2; n8++) {
                float* c = acc[mt][t16 * 2 + n8];
                int f0 = (g16 & 1) * 16 + n8 * 8 + tq * 2;
                #pragma unroll
                for (int e = 0; e < 4; e++) {
                    int row = rBase + ((e >> 1) << 3);
                    int f = f0 + (e & 1);
                    ro[(size_t)row * KF + f] = c[e];
                }
            }
        }
    }
}

// ---------------- fused: coef = sum of mode2 partials; h = coef @ gat_W; es/ed
__global__ __launch_bounds__(256) void k_hes(const float* __restrict__ gatW,
                                             const float* __restrict__ att_s,
                                             const float* __restrict__ att_d, int bbase) {
    __shared__ float Ws[2048];
    __shared__ float Cs[2048];
    __shared__ float Hs[64 * 65];
    int b = blockIdx.y + bbase;
    int rowBase = blockIdx.x * 64;
    int t = threadIdx.x;
    const float* Wb = gatW + b * 2048;
    const float* P0 = g_part + (size_t)b * KNF + (size_t)rowBase * KF;
    for (int i = t; i < 2048; i += 256) {
        Ws[i] = Wb[i];
        Cs[i] = P0[i] + P0[i + (size_t)13 * KNF] + P0[i + (size_t)26 * KNF];
    }
    __syncthreads();
    int col = t & 63, ns = t >> 6;
    for (int i = 0; i < 16; i++) {
        int n = i * 4 + ns;
        float acc = 0.f;
        #pragma unroll
        for (int k = 0; k < 32; k++) acc += Cs[n * 32 + k] * Ws[k * 64 + col];
        g_h[((size_t)b * KN + rowBase + n) * 64 + col] = acc;
        Hs[n * 65 + col] = acc;
    }
    __syncthreads();
    int row = t & 63, which = t >> 6;
    int h = which & 1, isD = which >> 1;
    const float* att = (isD ? att_d : att_s) + b * 64 + h * 32;
    float d = 0.f;
    #pragma unroll
    for (int f = 0; f < 32; f++) d += Hs[row * 65 + h * 32 + f] * att[f];
    float* dst = isD ? g_ed : g_es;
    dst[((size_t)b * KN + rowBase + row) * 2 + h] = d;
}

// ---------------- CSR build (deterministic) ----------------
__global__ void k_zero() {
    int i = blockIdx.x * blockDim.x + threadIdx.x;
    if (i < KN) g_deg[i] = 0;
}
__global__ void k_hist(const int* __restrict__ ei) {
    int e = blockIdx.x * blockDim.x + threadIdx.x;
    if (e < KE) atomicAdd(&g_deg[ei[KE + e]], 1);
}
__global__ __launch_bounds__(1024) void k_scan() {
    __shared__ int wsum[32];
    int t = threadIdx.x;
    int base = t * 4;
    int c[4], s = 0;
    #pragma unroll
    for (int i = 0; i < 4; i++) { c[i] = g_deg[base + i] + 1; s += c[i]; }
    int lane = t & 31, wid = t >> 5;
    int v = s;
    #pragma unroll
    for (int off = 1; off < 32; off <<= 1) {
        int u = __shfl_up_sync(0xffffffffu, v, off);
        if (lane >= off) v += u;
    }
    if (lane == 31) wsum[wid] = v;
    __syncthreads();
    if (t < 32) {
        int w = wsum[t];
        #pragma unroll
        for (int off = 1; off < 32; off <<= 1) {
            int u = __shfl_up_sync(0xffffffffu, w, off);
            if (t >= off) w += u;
        }
        wsum[t] = w;
    }
    __syncthreads();
    int woff = wid ? wsum[wid - 1] : 0;
    int run = woff + v - s;   // exclusive prefix
    #pragma unroll
    for (int i = 0; i < 4; i++) {
        g_rowptr[base + i] = run;
        g_pos[base + i] = run + 1;
        g_srcs[run] = KE + base + i;   // self loop as edge-id E+n (sorts last)
        run += c[i];
    }
    if (t == 1023) g_rowptr[KN] = run;
}
__global__ void k_fill(const int* __restrict__ ei) {
    int e = blockIdx.x * blockDim.x + threadIdx.x;
    if (e < KE) {
        int d = ei[KE + e];
        int slot = atomicAdd(&g_pos[d], 1);
        g_srcs[slot] = e;
    }
}
__global__ void k_sort(const int* __restrict__ ei) {
    int n = blockIdx.x * blockDim.x + threadIdx.x;
    if (n >= KN) return;
    int beg = g_rowptr[n], end = g_rowptr[n + 1];
    for (int i = beg + 1; i < end; i++) {     // insertion sort by edge id
        int key = g_srcs[i];
        int j = i - 1;
        while (j >= beg && g_srcs[j] > key) { g_srcs[j + 1] = g_srcs[j]; j--; }
        g_srcs[j + 1] = key;
    }
    for (int i = beg; i < end; i++) {         // edge id -> src node
        int id = g_srcs[i];
        g_srcs[i] = (id < KE) ? ei[id] : (id - KE);
    }
}

// ---------------- GAT softmax+agg + fused branch MLP (warp per (b,dst)) -------
__global__ __launch_bounds__(256) void k_gatmlp(const float* __restrict__ gatB,
                                                const float* __restrict__ mW,
                                                const float* __restrict__ mb,
                                                int bbase) {
    __shared__ float sE[8][2 * GCAP];
    __shared__ int   sS[8][GCAP];
    __shared__ float Wm[64 * 64];
    __shared__ float rowBuf[8][64];
    int w = threadIdx.x >> 5, lane = threadIdx.x & 31;
    int dst = blockIdx.x * 8 + w;
    int b = blockIdx.y + bbase;

    const float* Wb = mW + b * 4096;
    for (int i = threadIdx.x; i < 4096; i += 256) Wm[i] = Wb[i];
    __syncthreads();

    int beg = g_rowptr[dst], end = g_rowptr[dst + 1];
    int cnt = end - beg;
    const float* es = g_es + (long long)b * KN * 2;
    const float* ed = g_ed + (long long)b * KN * 2;
    float ed0 = ed[dst * 2], ed1 = ed[dst * 2 + 1];
    float acc0 = 0.f, acc1 = 0.f;
    float inv0, inv1;

    if (cnt <= GCAP) {
        float m0 = -1e30f, m1 = -1e30f;
        for (int i = lane; i < cnt; i += 32) {
            int s = g_srcs[beg + i];
            sS[w][i] = s;
            float e0 = lrelu(es[s * 2] + ed0);
            float e1 = lrelu(es[s * 2 + 1] + ed1);
            sE[w][2 * i] = e0;  sE[w][2 * i + 1] = e1;
            m0 = fmaxf(m0, e0); m1 = fmaxf(m1, e1);
        }
        #pragma unroll
        for (int off = 16; off; off >>= 1) {
            m0 = fmaxf(m0, __shfl_xor_sync(0xffffffffu, m0, off));
            m1 = fmaxf(m1, __shfl_xor_sync(0xffffffffu, m1, off));
        }
        float s0 = 0.f, s1 = 0.f;
        for (int i = lane; i < cnt; i += 32) {
            float w0 = __expf(sE[w][2 * i] - m0);
            float w1 = __expf(sE[w][2 * i + 1] - m1);
            sE[w][2 * i] = w0;  sE[w][2 * i + 1] = w1;
            s0 += w0;  s1 += w1;
        }
        #pragma unroll
        for (int off = 16; off; off >>= 1) {
            s0 += __shfl_xor_sync(0xffffffffu, s0, off);
            s1 += __shfl_xor_sync(0xffffffffu, s1, off);
        }
        inv0 = 1.f / (s0 + 1e-16f);  inv1 = 1.f / (s1 + 1e-16f);
        __syncwarp();
        #pragma unroll 4
        for (int i = 0; i < cnt; i++) {
            int s = sS[w][i];
            float w0 = sE[w][2 * i], w1 = sE[w][2 * i + 1];
            const float* hr = g_h + ((long long)b * KN + s) * 64;
            acc0 += w0 * hr[lane];
            acc1 += w1 * hr[32 + lane];
        }
        acc0 *= inv0;  acc1 *= inv1;
    } else {
        float m0 = -1e30f, m1 = -1e30f;
        for (int i = beg + lane; i < end; i += 32) {
            int s = g_srcs[i];
            m0 = fmaxf(m0, lrelu(es[s * 2] + ed0));
            m1 = fmaxf(m1, lrelu(es[s * 2 + 1] + ed1));
        }
        #pragma unroll
        for (int off = 16; off; off >>= 1) {
            m0 = fmaxf(m0, __shfl_xor_sync(0xffffffffu, m0, off));
            m1 = fmaxf(m1, __shfl_xor_sync(0xffffffffu, m1, off));
        }
        float s0 = 0.f, s1 = 0.f;
        for (int i = beg + lane; i < end; i += 32) {
            int s = g_srcs[i];
            s0 += __expf(lrelu(es[s * 2] + ed0) - m0);
            s1 += __expf(lrelu(es[s * 2 + 1] + ed1) - m1);
        }
        #pragma unroll
        for (int off = 16; off; off >>= 1) {
            s0 += __shfl_xor_sync(0xffffffffu, s0, off);
            s1 += __shfl_xor_sync(0xffffffffu, s1, off);
        }
        inv0 = 1.f / (s0 + 1e-16f);  inv1 = 1.f / (s1 + 1e-16f);
        for (int i = beg; i < end; i++) {
            int s = g_srcs[i];
            float a0 = __expf(lrelu(es[s * 2] + ed0) - m0);
            float a1 = __expf(lrelu(es[s * 2 + 1] + ed1) - m1);
            const float* hr = g_h + ((long long)b * KN + s) * 64;
            acc0 += a0 * hr[lane];
            acc1 += a1 * hr[32 + lane];
        }
        acc0 *= inv0;  acc1 *= inv1;
    }

    // gat activation, stage row in smem
    rowBuf[w][lane]      = eluf(acc0 + gatB[b * 64 + lane]);
    rowBuf[w][32 + lane] = eluf(acc1 + gatB[b * 64 + 32 + lane]);
    __syncwarp();

    // fused branch MLP: lane computes cols (lane, lane+32); same k-order as k_mlp
    float a0 = mb[b * 64 + lane], a1 = mb[b * 64 + 32 + lane];
    #pragma unroll
    for (int k = 0; k < 64; k++) {
        float v = rowBuf[w][k];
        a0 += v * Wm[k * 64 + lane];
        a1 += v * Wm[k * 64 + 32 + lane];
    }
    float* fr = g_feat + (size_t)dst * (KG * KNHID) + b * 64;
    fr[lane] = a0;
    fr[32 + lane] = a1;
}

// ---------------- final head + log_softmax (warp per node) ----------------
__global__ __launch_bounds__(256) void k_final(const float* __restrict__ oW,
                                               const float* __restrict__ ob,
                                               float* __restrict__ out) {
    int w = threadIdx.x >> 5, lane = threadIdx.x & 31;
    int n = blockIdx.x * 8 + w;
    const float* fr = g_feat + (long long)n * (KG * KNHID);
    float acc[KC];
    #pragma unroll
    for (int c = 0; c < KC; c++) acc[c] = 0.f;
    for (int k = lane; k < KG * KNHID; k += 32) {
        float v = eluf(fr[k]);
        #pragma unroll
        for (int c = 0; c < KC; c++) acc[c] += v * oW[k * KC + c];
    }
    #pragma unroll
    for (int c = 0; c < KC; c++)
        #pragma unroll
        for (int off = 16; off; off >>= 1)
            acc[c] += __shfl_xor_sync(0xffffffffu, acc[c], off);
    if (lane == 0) {
        float l[KC], m = -1e30f;
        #pragma unroll
        for (int c = 0; c < KC; c++) { l[c] = acc[c] + ob[c]; m = fmaxf(m, l[c]); }
        float se = 0.f;
        #pragma unroll
        for (int c = 0; c < KC; c++) se += expf(l[c] - m);
        float lse = logf(se) + m;
        #pragma unroll
        for (int c = 0; c < KC; c++) out[(long long)n * KC + c] = l[c] - lse;
    }
}

// ---------------- launch ----------------
static inline int smemBytes(int nb, bool aext) {
    return 1024 + (aext ? 49152 : 32768) + nb * 6 * 2048;
}

extern "C" void kernel_launch(void* const* d_in, const int* in_sizes, int n_in,
                              void* d_out, int out_size) {
    (void)in_sizes; (void)n_in; (void)out_size;
    const float* x     = (const float*)d_in[0];
    const int*   ei    = (const int*)d_in[1];
    const float* U     = (const float*)d_in[2];
    const float* psi   = (const float*)d_in[3];
    const float* gatW  = (const float*)d_in[4];
    const float* att_s = (const float*)d_in[5];
    const float* att_d = (const float*)d_in[6];
    const float* gatB  = (const float*)d_in[7];
    const float* mlpW  = (const float*)d_in[8];
    const float* mlpB  = (const float*)d_in[9];
    const float* outW  = (const float*)d_in[10];
    const float* outB  = (const float*)d_in[11];
    float* out = (float*)d_out;

    static cudaStream_t s2 = nullptr;
    static cudaEvent_t evRoot, evConvU, evRed2, evNB1, evCoef, evS2;
    if (!s2) {
        cudaStreamCreateWithFlags(&s2, cudaStreamNonBlocking);
        cudaEventCreateWithFlags(&evRoot, cudaEventDisableTiming);
        cudaEventCreateWithFlags(&evConvU, cudaEventDisableTiming);
        cudaEventCreateWithFlags(&evRed2, cudaEventDisableTiming);
        cudaEventCreateWithFlags(&evNB1, cudaEventDisableTiming);
        cudaEventCreateWithFlags(&evCoef, cudaEventDisableTiming);
        cudaEventCreateWithFlags(&evS2, cudaEventDisableTiming);
    }

    cudaFuncSetAttribute((const void*)k_mma<1, true, false>, cudaFuncAttributeMaxDynamicSharedMemorySize, smemBytes(1, false));
    cudaFuncSetAttribute((const void*)k_mma<3, true, false>, cudaFuncAttributeMaxDynamicSharedMemorySize, smemBytes(3, false));
    cudaFuncSetAttribute((const void*)k_mma<4, false, true>, cudaFuncAttributeMaxDynamicSharedMemorySize, smemBytes(4, true));
    cudaFuncSetAttribute((const void*)k_mma<1, false, true>, cudaFuncAttributeMaxDynamicSharedMemorySize, smemBytes(1, true));
    cudaFuncSetAttribute((const void*)k_mma<1, true, false>, cudaFuncAttributePreferredSharedMemoryCarveout, 100);
    cudaFuncSetAttribute((const void*)k_mma<3, true, false>, cudaFuncAttributePreferredSharedMemoryCarveout, 100);
    cudaFuncSetAttribute((const void*)k_mma<4, false, true>, cudaFuncAttributePreferredSharedMemoryCarveout, 100);
    cudaFuncSetAttribute((const void*)k_mma<1, false, true>, cudaFuncAttributePreferredSharedMemoryCarveout, 100);

    // ---- fork side stream ----
    cudaEventRecord(evRoot, 0);
    cudaStreamWaitEvent(s2, evRoot, 0);

    k_convU<<<(int)((KNN / 4 + 255) / 256), 256, 0, s2>>>(U);
    cudaEventRecord(evConvU, s2);
    k_zero<<<16, 256, 0, s2>>>();
    k_hist<<<KE / 256, 256, 0, s2>>>(ei);
    k_scan<<<1, 1024, 0, s2>>>();
    k_fill<<<KE / 256, 256, 0, s2>>>(ei);
    k_sort<<<16, 256, 0, s2>>>(ei);

    // ---- main chain: psi passes ----
    k_absT2<<<32, 256>>>(x);
    k_mma<1, true, false><<<dim3(32, 3, 3), 256, smemBytes(1, false)>>>(0, U, psi, 0); // L1
    k_redT<<<dim3(64, 3), 256>>>(3 * KNF, 1);                                          // -> B 1..3
    k_mma<3, true, false><<<dim3(32, 3, 3), 256, smemBytes(3, false)>>>(1, U, psi, 0); // L2
    k_redT<<<dim3(64, 9), 256>>>(9 * KNF, 4);                                          // -> B 4..12
    cudaEventRecord(evRed2, 0);

    // ---- main: coef slots 0..11 (one clean launch) ----
    cudaStreamWaitEvent(0, evConvU, 0);
    k_mma<4, false, true><<<dim3(32, 3, 3), 256, smemBytes(4, true)>>>(2, U, psi, 0);  // coef 0..11
    cudaEventRecord(evCoef, 0);

    // ---- s2: coef slot 12 overlaps; then hes+gat b0..3 (after main coef!) ----
    cudaStreamWaitEvent(s2, evRed2, 0);
    k_mma<1, false, true><<<dim3(32, 1, 3), 256, smemBytes(1, true), s2>>>(2, U, psi, 0); // coef 12
    cudaEventRecord(evNB1, s2);
    cudaStreamWaitEvent(s2, evCoef, 0);      // hes b0..3 reads g_part 0..3/13..16/26..29
    k_hes<<<dim3(64, 4), 256, 0, s2>>>(gatW, att_s, att_d, 0);                            // hes b0..3
    k_gatmlp<<<dim3(KN / 8, 4), 256, 0, s2>>>(gatB, mlpW, mlpB, 0);                       // gat b0..3
    cudaEventRecord(evS2, s2);

    // ---- main: hes + gat b4..12 ----
    cudaStreamWaitEvent(0, evNB1, 0);
    k_hes<<<dim3(64, 9), 256>>>(gatW, att_s, att_d, 4);                                   // hes b4..12
    k_gatmlp<<<dim3(KN / 8, 9), 256>>>(gatB, mlpW, mlpB, 4);                              // gat b4..12

    // ---- join + final ----
    cudaStreamWaitEvent(0, evS2, 0);
    k_final<<<KN / 8, 256>>>(outW, outB, out);
}

// round 17
// speedup vs baseline: 1.0381x; 1.0381x over previous
#include <cuda_runtime.h>
#include <cuda_bf16.h>
#include <cstdint>

// Problem constants
#define KN 4096      // nodes
#define KF 32        // features
#define KHF 64       // heads*features
#define KNHID 64
#define KC 10
#define KE 65536     // edges
#define KG 13        // branches
#define KNN (KN*KN)
#define KNF (KN*KF)
#define GCAP 192     // max cached degree per dst
#define COEF_OFF 39  // coef partials live at g_part + COEF_OFF*KNF (disjoint from psi partials)

// ---------------- device scratch (no allocations allowed) ----------------
__device__ __align__(128) __nv_bfloat16 g_Bh[KG * KF * KN]; // B operands [slot][f][node]
__device__ __align__(128) __nv_bfloat16 g_Bl[KG * KF * KN];
__device__ __align__(128) __nv_bfloat16 g_Uh[KNN];          // U bf16 hi
__device__ __align__(128) __nv_bfloat16 g_Ul[KNN];          // U bf16 lo
__device__ float g_part[78ull * KN * KF]; // [0..38] psi split-K, [39..77] coef split-K
__device__ float g_h[KG * KN * KHF];     // per-branch GAT hidden [13][N][64]
__device__ float g_es[KG * KN * 2];
__device__ float g_ed[KG * KN * 2];
__device__ float g_feat[KN * KG * KNHID];// [N][832]
__device__ int   g_deg[KN];
__device__ int   g_rowptr[KN + 1];
__device__ int   g_pos[KN];
__device__ int   g_srcs[KE + KN];

// ---------------- helpers ----------------
__device__ __forceinline__ float lrelu(float v) { return v > 0.f ? v : 0.2f * v; }
__device__ __forceinline__ float eluf(float v)  { return v > 0.f ? v : expm1f(v); }

__device__ __forceinline__ uint32_t su32(const void* p) {
    return (uint32_t)__cvta_generic_to_shared(p);
}
__device__ __forceinline__ void cpa16(uint32_t dst, const void* src) {
    asm volatile("cp.async.cg.shared.global [%0], [%1], 16;" :: "r"(dst), "l"(src) : "memory");
}
__device__ __forceinline__ uint32_t swz64(uint32_t off) { return off ^ ((off >> 3) & 0x30); }

#define LDSM4(d, addr) \
    asm volatile("ldmatrix.sync.aligned.m8n8.x4.shared.b16 {%0,%1,%2,%3}, [%4];" \
        : "=r"((d)[0]), "=r"((d)[1]), "=r"((d)[2]), "=r"((d)[3]) : "r"(addr))

__device__ __forceinline__ void mma_bf16(float* c, const uint32_t* a,
                                         uint32_t b0, uint32_t b1) {
    asm volatile("mma.sync.aligned.m16n8k16.row.col.f32.bf16.bf16.f32 "
        "{%0,%1,%2,%3}, {%4,%5,%6,%7}, {%8,%9}, {%0,%1,%2,%3};"
        : "+f"(c[0]), "+f"(c[1]), "+f"(c[2]), "+f"(c[3])
        : "r"(a[0]), "r"(a[1]), "r"(a[2]), "r"(a[3]), "r"(b0), "r"(b1));
}

__device__ __forceinline__ uint32_t pack_bf16(__nv_bfloat16 a, __nv_bfloat16 b) {
    __nv_bfloat162 t(a, b);
    return *(uint32_t*)&t;
}

// ---------------- |x| -> transposed bf16 split (B slot 0) ----------------
__global__ __launch_bounds__(256) void k_absT2(const float* __restrict__ x) {
    __shared__ float T[32 * 129];
    int nodeBase = blockIdx.x * 128;
    int t = threadIdx.x;
    const float* src = x + (size_t)nodeBase * 32;
    for (int i = t; i < 4096; i += 256) {
        int node = i >> 5, f = i & 31;
        T[f * 129 + node] = fabsf(src[i]);
    }
    __syncthreads();
    for (int i = t; i < 4096; i += 256) {
        int f = i >> 7, node = i & 127;
        float v = T[f * 129 + node];
        __nv_bfloat16 h = __float2bfloat16(v);
        size_t o = (size_t)f * KN + nodeBase + node;
        g_Bh[o] = h;
        g_Bl[o] = __float2bfloat16(v - __bfloat162float(h));
    }
}

// ---------------- U fp32 -> bf16 hi/lo (elementwise, coalesced) ----------------
__global__ __launch_bounds__(256) void k_convU(const float* __restrict__ U) {
    size_t i = ((size_t)blockIdx.x * 256 + threadIdx.x) * 4;
    if (i >= (size_t)KNN) return;
    float4 v = *(const float4*)(U + i);
    __nv_bfloat16 h0 = __float2bfloat16(v.x), h1 = __float2bfloat16(v.y);
    __nv_bfloat16 h2 = __float2bfloat16(v.z), h3 = __float2bfloat16(v.w);
    *(uint2*)(g_Uh + i) = make_uint2(pack_bf16(h0, h1), pack_bf16(h2, h3));
    *(uint2*)(g_Ul + i) = make_uint2(
        pack_bf16(__float2bfloat16(v.x - __bfloat162float(h0)),
                  __float2bfloat16(v.y - __bfloat162float(h1))),
        pack_bf16(__float2bfloat16(v.z - __bfloat162float(h2)),
                  __float2bfloat16(v.w - __bfloat162float(h3))));
}

// ---------------- split-K reduce + abs + bf16-split, 64-node tiles ----------
__global__ __launch_bounds__(256) void k_redT(int stride, int outBase) {
    __shared__ float T[32 * 65];
    int lin = blockIdx.y;
    int nodeBase = blockIdx.x * 64;
    int t = threadIdx.x;
    const float* p0 = g_part + (size_t)lin * KNF + (size_t)nodeBase * 32;
    for (int i = t; i < 2048; i += 256) {
        int node = i >> 5, f = i & 31;
        T[f * 65 + node] = fabsf(p0[i] + p0[i + (size_t)stride] + p0[i + 2 * (size_t)stride]);
    }
    __syncthreads();
    for (int i = t; i < 2048; i += 256) {
        int f = i >> 6, node = i & 63;
        float v = T[f * 65 + node];
        __nv_bfloat16 h = __float2bfloat16(v);
        size_t o = (size_t)(outBase + lin) * KNF + (size_t)f * KN + nodeBase + node;
        g_Bh[o] = h;
        g_Bl[o] = __float2bfloat16(v - __bfloat162float(h));
    }
}

// ---------------- mma.sync scattering GEMM ----------------
// mode 0 (NB1,PREF):  A=psi_y fp32 inline-split, in slot0,  partial z*3+y.  (32,3,3)
// mode 1 (NB3,PREF):  A=psi_y fp32 inline-split, in {1,2,3}, partial z*9+3b+y. (32,3,3)
// mode 2 (NB4,AEXT):  A=g_Uh/g_Ul cp.async, in {4y+b}, partial COEF_OFF+z*13+slot.
// mode 2 (NB1,AEXT):  A=g_Uh/g_Ul cp.async, in {12},   partial COEF_OFF+z*13+12.
template <int NB, bool PREF, bool AEXT>
__global__ __launch_bounds__(256, 2) void k_mma(int mode, const float* __restrict__ U,
                                                const float* __restrict__ psi, int ybase) {
    extern __shared__ char dsm[];
    int tid = threadIdx.x;
    uint32_t sraw = su32(dsm);
    uint32_t sbase = (sraw + 1023u) & ~1023u;
    char* smp = dsm + (sbase - sraw);          // generic pointer to aligned base

    int y = blockIdx.y + ybase;
    int z = blockIdx.z;
    int rowBase = blockIdx.x * 128;
    int slotIn[NB], rawIdx[NB];
    const float* Afp = nullptr;
    int cBeg = (z * 128) / 3, cEnd = ((z + 1) * 128) / 3;   // chunk32 indices
    if (mode == 0) {
        Afp = psi + (size_t)y * KNN;
        slotIn[0] = 0; rawIdx[0] = z * 3 + y;
    } else if (mode == 1) {
        Afp = psi + (size_t)y * KNN;
        #pragma unroll
        for (int b = 0; b < NB; b++) { slotIn[b] = 1 + b; rawIdx[b] = z * 9 + 3 * b + y; }
    } else {
        #pragma unroll
        for (int b = 0; b < NB; b++) {
            int s = (NB == 1) ? 12 : (4 * y + b);
            slotIn[b] = s; rawIdx[b] = COEF_OFF + z * 13 + s;
        }
    }

    constexpr uint32_t ABytes = AEXT ? 49152u : 32768u;
    auto A_at = [&](int st, int p) { return sbase + (uint32_t)(st * 2 + p) * 8192u; };
    auto A_off = [&](int st, int p) { return (uint32_t)(st * 2 + p) * 8192u; };
    auto B_at = [&](int st, int p, int b) {
        return sbase + ABytes + (uint32_t)((st * 2 + p) * NB + b) * 2048u;
    };

    float buf[PREF ? 16 : (AEXT ? 1 : 16)];
    auto ldgA = [&](int c) {
        if (AEXT) return;
        #pragma unroll
        for (int it = 0; it < 4; it++) {
            int i = it * 256 + tid;
            int r = i >> 3, seg = i & 7;
            *(float4*)(buf + it * 4) =
                *(const float4*)(Afp + (size_t)(rowBase + r) * KN + c * 32 + seg * 4);
        }
    };
    auto stsA = [&](int st) {
        if (AEXT) return;
        #pragma unroll
        for (int it = 0; it < 4; it++) {
            int i = it * 256 + tid;
            int r = i >> 3, seg = i & 7;
            float v0 = buf[it * 4 + 0], v1 = buf[it * 4 + 1];
            float v2 = buf[it * 4 + 2], v3 = buf[it * 4 + 3];
            __nv_bfloat16 h0 = __float2bfloat16(v0), h1 = __float2bfloat16(v1);
            __nv_bfloat16 h2 = __float2bfloat16(v2), h3 = __float2bfloat16(v3);
            uint2 hi = make_uint2(pack_bf16(h0, h1), pack_bf16(h2, h3));
            uint2 lo = make_uint2(
                pack_bf16(__float2bfloat16(v0 - __bfloat162float(h0)),
                          __float2bfloat16(v1 - __bfloat162float(h1))),
                pack_bf16(__float2bfloat16(v2 - __bfloat162float(h2)),
                          __float2bfloat16(v3 - __bfloat162float(h3))));
            uint32_t off = swz64((uint32_t)(r * 64 + seg * 8));
            *(uint2*)(smp + A_off(st, 0) + off) = hi;
            *(uint2*)(smp + A_off(st, 1) + off) = lo;
        }
    };
    auto ldAext = [&](int c, int s) {     // AEXT: A via cp.async from g_Uh/g_Ul
        int k0 = c * 32;
        #pragma unroll
        for (int it = 0; it < 2; it++) {
            int i = it * 256 + tid;       // 512 16B segs per part
            int r = i >> 2, seg = i & 3;
            uint32_t sw = swz64((uint32_t)(r * 64 + seg * 16));
            size_t go = (size_t)(rowBase + r) * KN + k0 + seg * 8;
            cpa16(A_at(s, 0) + sw, g_Uh + go);
            cpa16(A_at(s, 1) + sw, g_Ul + go);
        }
    };

    auto ldB = [&](int c, int s) {
        int k0 = c * 32;
        if (tid < 128) {
            int r = tid >> 2, seg = tid & 3;
            uint32_t sw = swz64((uint32_t)(r * 64 + seg * 16));
            #pragma unroll
            for (int b = 0; b < NB; b++) {
                size_t go = (size_t)slotIn[b] * (KF * KN) + (size_t)r * KN + k0 + seg * 8;
                cpa16(B_at(s, 0, b) + sw, g_Bh + go);
                cpa16(B_at(s, 1, b) + sw, g_Bl + go);
            }
        }
    };

    int wid = tid >> 5, lane = tid & 31;
    int wm = wid >> 1, wn = wid & 1;       // 4 M-warps x 2 N-warps

    auto aAddr = [&](uint32_t base, int mt, int q) {
        int row = wm * 32 + mt * 16 + (lane & 15);
        int colb = q * 32 + ((lane >> 4) << 4);
        return base + swz64((uint32_t)(row * 64 + colb));
    };
    auto bAddr = [&](uint32_t base, int n0, int q) {
        int j = lane >> 3, r = lane & 7;
        int row = n0 + ((j >> 1) << 3) + r;
        int colb = q * 32 + ((j & 1) << 4);
        return base + swz64((uint32_t)(row * 64 + colb));
    };

    float acc[2][2 * NB][4];
    #pragma unroll
    for (int mt = 0; mt < 2; mt++)
        #pragma unroll
        for (int n = 0; n < 2 * NB; n++)
            #pragma unroll
            for (int e = 0; e < 4; e++) acc[mt][n][e] = 0.f;

    // prologue
    if (AEXT) {
        ldAext(cBeg, 0);
        ldB(cBeg, 0);
        asm volatile("cp.async.commit_group;" ::: "memory");
        if (cBeg + 1 < cEnd) { ldAext(cBeg + 1, 1); ldB(cBeg + 1, 1); }
        asm volatile("cp.async.commit_group;" ::: "memory");
    } else {
        if (PREF) {
            ldgA(cBeg);
            stsA(0);
            if (cBeg + 1 < cEnd) ldgA(cBeg + 1);
        }
        ldB(cBeg, 0);
        asm volatile("cp.async.commit_group;" ::: "memory");
        if (cBeg + 1 < cEnd) ldB(cBeg + 1, 1);
        asm volatile("cp.async.commit_group;" ::: "memory");
        if (!PREF) {
            ldgA(cBeg);
            stsA(0);
        }
    }

    for (int i = cBeg; i < cEnd; i++) {
        int sA = AEXT ? ((i - cBeg) % 3) : ((i - cBeg) & 1);
        int sB = (i - cBeg) % 3;
        asm volatile("cp.async.wait_group 1;" ::: "memory");
        __syncthreads();
        if (i + 2 < cEnd) {
            if (AEXT) ldAext(i + 2, (i - cBeg + 2) % 3);
            ldB(i + 2, (i - cBeg + 2) % 3);
        }
        asm volatile("cp.async.commit_group;" ::: "memory");
        if (!AEXT) {
            if (PREF) {
                if (i + 1 < cEnd) {
                    stsA(sA ^ 1);
                    if (i + 2 < cEnd) ldgA(i + 2);
                }
            } else {
                if (i + 1 < cEnd) {
                    ldgA(i + 1);
                    stsA(sA ^ 1);
                }
            }
        }

        #pragma unroll
        for (int q = 0; q < 2; q++) {
            uint32_t ah[2][4], al[2][4];
            #pragma unroll
            for (int mt = 0; mt < 2; mt++) {
                LDSM4(ah[mt], aAddr(A_at(sA, 0), mt, q));
                LDSM4(al[mt], aAddr(A_at(sA, 1), mt, q));
            }
            #pragma unroll
            for (int t16 = 0; t16 < NB; t16++) {
                int g16 = wn * NB + t16;
                int b = g16 >> 1, n0 = (g16 & 1) * 16;
                uint32_t bh[4], bl[4];
                LDSM4(bh, bAddr(B_at(sB, 0, b), n0, q));
                LDSM4(bl, bAddr(B_at(sB, 1, b), n0, q));
                #pragma unroll
                for (int n8 = 0; n8 < 2; n8++) {
                    uint32_t h0 = bh[2 * n8], h1 = bh[2 * n8 + 1];
                    uint32_t l0 = bl[2 * n8], l1 = bl[2 * n8 + 1];
                    #pragma unroll
                    for (int mt = 0; mt < 2; mt++) {
                        float* c = acc[mt][t16 * 2 + n8];
                        mma_bf16(c, ah[mt], h0, h1);
                        mma_bf16(c, ah[mt], l0, l1);
                        mma_bf16(c, al[mt], h0, h1);
                    }
                }
            }
        }
    }

    // epilogue: raw fp32 partial stores
    int quad = lane >> 2, tq = lane & 3;
    #pragma unroll
    for (int mt = 0; mt < 2; mt++) {
        int rBase = rowBase + wm * 32 + mt * 16 + quad;
        #pragma unroll
        for (int t16 = 0; t16 < NB; t16++) {
            int g16 = wn * NB + t16;
            int b = g16 >> 1;
            float* ro = g_part + (size_t)rawIdx[b] * (KN * KF);
            #pragma unroll
            for (int n8 = 0; n8 < 2; n8++) {
                float* c = acc[mt][t16 * 2 + n8];
                int f0 = (g16 & 1) * 16 + n8 * 8 + tq * 2;
                #pragma unroll
                for (int e = 0; e < 4; e++) {
                    int row = rBase + ((e >> 1) << 3);
                    int f = f0 + (e & 1);
                    ro[(size_t)row * KF + f] = c[e];
                }
            }
        }
    }
}

// ---------------- fused: coef = sum of coef partials; h = coef @ gat_W; es/ed
__global__ __launch_bounds__(256) void k_hes(const float* __restrict__ gatW,
                                             const float* __restrict__ att_s,
                                             const float* __restrict__ att_d, int bbase) {
    __shared__ float Ws[2048];
    __shared__ float Cs[2048];
    __shared__ float Hs[64 * 65];
    int b = blockIdx.y + bbase;
    int rowBase = blockIdx.x * 64;
    int t = threadIdx.x;
    const float* Wb = gatW + b * 2048;
    const float* P0 = g_part + (size_t)(COEF_OFF + b) * KNF + (size_t)rowBase * KF;
    for (int i = t; i < 2048; i += 256) {
        Ws[i] = Wb[i];
        Cs[i] = P0[i] + P0[i + (size_t)13 * KNF] + P0[i + (size_t)26 * KNF];
    }
    __syncthreads();
    int col = t & 63, ns = t >> 6;
    for (int i = 0; i < 16; i++) {
        int n = i * 4 + ns;
        float acc = 0.f;
        #pragma unroll
        for (int k = 0; k < 32; k++) acc += Cs[n * 32 + k] * Ws[k * 64 + col];
        g_h[((size_t)b * KN + rowBase + n) * 64 + col] = acc;
        Hs[n * 65 + col] = acc;
    }
    __syncthreads();
    int row = t & 63, which = t >> 6;
    int h = which & 1, isD = which >> 1;
    const float* att = (isD ? att_d : att_s) + b * 64 + h * 32;
    float d = 0.f;
    #pragma unroll
    for (int f = 0; f < 32; f++) d += Hs[row * 65 + h * 32 + f] * att[f];
    float* dst = isD ? g_ed : g_es;
    dst[((size_t)b * KN + rowBase + row) * 2 + h] = d;
}

// ---------------- CSR build (deterministic) ----------------
__global__ void k_zero() {
    int i = blockIdx.x * blockDim.x + threadIdx.x;
    if (i < KN) g_deg[i] = 0;
}
__global__ void k_hist(const int* __restrict__ ei) {
    int e = blockIdx.x * blockDim.x + threadIdx.x;
    if (e < KE) atomicAdd(&g_deg[ei[KE + e]], 1);
}
__global__ __launch_bounds__(1024) void k_scan() {
    __shared__ int wsum[32];
    int t = threadIdx.x;
    int base = t * 4;
    int c[4], s = 0;
    #pragma unroll
    for (int i = 0; i < 4; i++) { c[i] = g_deg[base + i] + 1; s += c[i]; }
    int lane = t & 31, wid = t >> 5;
    int v = s;
    #pragma unroll
    for (int off = 1; off < 32; off <<= 1) {
        int u = __shfl_up_sync(0xffffffffu, v, off);
        if (lane >= off) v += u;
    }
    if (lane == 31) wsum[wid] = v;
    __syncthreads();
    if (t < 32) {
        int w = wsum[t];
        #pragma unroll
        for (int off = 1; off < 32; off <<= 1) {
            int u = __shfl_up_sync(0xffffffffu, w, off);
            if (t >= off) w += u;
        }
        wsum[t] = w;
    }
    __syncthreads();
    int woff = wid ? wsum[wid - 1] : 0;
    int run = woff + v - s;   // exclusive prefix
    #pragma unroll
    for (int i = 0; i < 4; i++) {
        g_rowptr[base + i] = run;
        g_pos[base + i] = run + 1;
        g_srcs[run] = KE + base + i;   // self loop as edge-id E+n (sorts last)
        run += c[i];
    }
    if (t == 1023) g_rowptr[KN] = run;
}
__global__ void k_fill(const int* __restrict__ ei) {
    int e = blockIdx.x * blockDim.x + threadIdx.x;
    if (e < KE) {
        int d = ei[KE + e];
        int slot = atomicAdd(&g_pos[d], 1);
        g_srcs[slot] = e;
    }
}
__global__ void k_sort(const int* __restrict__ ei) {
    int n = blockIdx.x * blockDim.x + threadIdx.x;
    if (n >= KN) return;
    int beg = g_rowptr[n], end = g_rowptr[n + 1];
    for (int i = beg + 1; i < end; i++) {     // insertion sort by edge id
        int key = g_srcs[i];
        int j = i - 1;
        while (j >= beg && g_srcs[j] > key) { g_srcs[j + 1] = g_srcs[j]; j--; }
        g_srcs[j + 1] = key;
    }
    for (int i = beg; i < end; i++) {         // edge id -> src node
        int id = g_srcs[i];
        g_srcs[i] = (id < KE) ? ei[id] : (id - KE);
    }
}

// ------ GAT softmax+agg + fused branch MLP (warp per dst, 4 dst/warp) --------
__global__ __launch_bounds__(256) void k_gatmlp(const float* __restrict__ gatB,
                                                const float* __restrict__ mW,
                                                const float* __restrict__ mb,
                                                int bbase) {
    __shared__ float sE[8][2 * GCAP];
    __shared__ int   sS[8][GCAP];
    __shared__ float Wm[64 * 64];
    __shared__ float rowBuf[8][64];
    int w = threadIdx.x >> 5, lane = threadIdx.x & 31;
    int b = blockIdx.y + bbase;

    const float* Wb = mW + b * 4096;
    for (int i = threadIdx.x; i < 4096; i += 256) Wm[i] = Wb[i];
    __syncthreads();

    const float* es = g_es + (long long)b * KN * 2;
    const float* ed = g_ed + (long long)b * KN * 2;
    float gb0 = gatB[b * 64 + lane],  gb1 = gatB[b * 64 + 32 + lane];
    float bias0 = mb[b * 64 + lane],  bias1 = mb[b * 64 + 32 + lane];

    for (int it = 0; it < 4; it++) {
        int dst = blockIdx.x * 32 + it * 8 + w;
        int beg = g_rowptr[dst], end = g_rowptr[dst + 1];
        int cnt = end - beg;
        float ed0 = ed[dst * 2], ed1 = ed[dst * 2 + 1];
        float acc0 = 0.f, acc1 = 0.f;
        float inv0, inv1;

        if (cnt <= GCAP) {
            float m0 = -1e30f, m1 = -1e30f;
            for (int i = lane; i < cnt; i += 32) {
                int s = g_srcs[beg + i];
                sS[w][i] = s;
                float e0 = lrelu(es[s * 2] + ed0);
                float e1 = lrelu(es[s * 2 + 1] + ed1);
                sE[w][2 * i] = e0;  sE[w][2 * i + 1] = e1;
                m0 = fmaxf(m0, e0); m1 = fmaxf(m1, e1);
            }
            #pragma unroll
            for (int off = 16; off; off >>= 1) {
                m0 = fmaxf(m0, __shfl_xor_sync(0xffffffffu, m0, off));
                m1 = fmaxf(m1, __shfl_xor_sync(0xffffffffu, m1, off));
            }
            float s0 = 0.f, s1 = 0.f;
            for (int i = lane; i < cnt; i += 32) {
                float w0 = __expf(sE[w][2 * i] - m0);
                float w1 = __expf(sE[w][2 * i + 1] - m1);
                sE[w][2 * i] = w0;  sE[w][2 * i + 1] = w1;
                s0 += w0;  s1 += w1;
            }
            #pragma unroll
            for (int off = 16; off; off >>= 1) {
                s0 += __shfl_xor_sync(0xffffffffu, s0, off);
                s1 += __shfl_xor_sync(0xffffffffu, s1, off);
            }
            inv0 = 1.f / (s0 + 1e-16f);  inv1 = 1.f / (s1 + 1e-16f);
            __syncwarp();
            #pragma unroll 4
            for (int i = 0; i < cnt; i++) {
                int s = sS[w][i];
                float w0 = sE[w][2 * i], w1 = sE[w][2 * i + 1];
                const float* hr = g_h + ((long long)b * KN + s) * 64;
                acc0 += w0 * hr[lane];
                acc1 += w1 * hr[32 + lane];
            }
            acc0 *= inv0;  acc1 *= inv1;
        } else {
            float m0 = -1e30f, m1 = -1e30f;
            for (int i = beg + lane; i < end; i += 32) {
                int s = g_srcs[i];
                m0 = fmaxf(m0, lrelu(es[s * 2] + ed0));
                m1 = fmaxf(m1, lrelu(es[s * 2 + 1] + ed1));
            }
            #pragma unroll
            for (int off = 16; off; off >>= 1) {
                m0 = fmaxf(m0, __shfl_xor_sync(0xffffffffu, m0, off));
                m1 = fmaxf(m1, __shfl_xor_sync(0xffffffffu, m1, off));
            }
            float s0 = 0.f, s1 = 0.f;
            for (int i = beg + lane; i < end; i += 32) {
                int s = g_srcs[i];
                s0 += __expf(lrelu(es[s * 2] + ed0) - m0);
                s1 += __expf(lrelu(es[s * 2 + 1] + ed1) - m1);
            }
            #pragma unroll
            for (int off = 16; off; off >>= 1) {
                s0 += __shfl_xor_sync(0xffffffffu, s0, off);
                s1 += __shfl_xor_sync(0xffffffffu, s1, off);
            }
            inv0 = 1.f / (s0 + 1e-16f);  inv1 = 1.f / (s1 + 1e-16f);
            for (int i = beg; i < end; i++) {
                int s = g_srcs[i];
                float a0 = __expf(lrelu(es[s * 2] + ed0) - m0);
                float a1 = __expf(lrelu(es[s * 2 + 1] + ed1) - m1);
                const float* hr = g_h + ((long long)b * KN + s) * 64;
                acc0 += a0 * hr[lane];
                acc1 += a1 * hr[32 + lane];
            }
            acc0 *= inv0;  acc1 *= inv1;
        }

        // gat activation, stage row in smem (per-warp buffer)
        rowBuf[w][lane]      = eluf(acc0 + gb0);
        rowBuf[w][32 + lane] = eluf(acc1 + gb1);
        __syncwarp();

        // fused branch MLP: lane computes cols (lane, lane+32); same k-order as k_mlp
        float a0 = bias0, a1 = bias1;
        #pragma unroll
        for (int k = 0; k < 64; k++) {
            float v = rowBuf[w][k];
            a0 += v * Wm[k * 64 + lane];
            a1 += v * Wm[k * 64 + 32 + lane];
        }
        float* fr = g_feat + (size_t)dst * (KG * KNHID) + b * 64;
        fr[lane] = a0;
        fr[32 + lane] = a1;
        __syncwarp();   // protect rowBuf/sE reuse next iteration
    }
}

// ---------------- final head + log_softmax (warp per node) ----------------
__global__ __launch_bounds__(256) void k_final(const float* __restrict__ oW,
                                               const float* __restrict__ ob,
                                               float* __restrict__ out) {
    int w = threadIdx.x >> 5, lane = threadIdx.x & 31;
    int n = blockIdx.x * 8 + w;
    const float* fr = g_feat + (long long)n * (KG * KNHID);
    float acc[KC];
    #pragma unroll
    for (int c = 0; c < KC; c++) acc[c] = 0.f;
    for (int k = lane; k < KG * KNHID; k += 32) {
        float v = eluf(fr[k]);
        #pragma unroll
        for (int c = 0; c < KC; c++) acc[c] += v * oW[k * KC + c];
    }
    #pragma unroll
    for (int c = 0; c < KC; c++)
        #pragma unroll
        for (int off = 16; off; off >>= 1)
            acc[c] += __shfl_xor_sync(0xffffffffu, acc[c], off);
    if (lane == 0) {
        float l[KC], m = -1e30f;
        #pragma unroll
        for (int c = 0; c < KC; c++) { l[c] = acc[c] + ob[c]; m = fmaxf(m, l[c]); }
        float se = 0.f;
        #pragma unroll
        for (int c = 0; c < KC; c++) se += expf(l[c] - m);
        float lse = logf(se) + m;
        #pragma unroll
        for (int c = 0; c < KC; c++) out[(long long)n * KC + c] = l[c] - lse;
    }
}

// ---------------- launch ----------------
static inline int smemBytes(int nb, bool aext) {
    return 1024 + (aext ? 49152 : 32768) + nb * 6 * 2048;
}

extern "C" void kernel_launch(void* const* d_in, const int* in_sizes, int n_in,
                              void* d_out, int out_size) {
    (void)in_sizes; (void)n_in; (void)out_size;
    const float* x     = (const float*)d_in[0];
    const int*   ei    = (const int*)d_in[1];
    const float* U     = (const float*)d_in[2];
    const float* psi   = (const float*)d_in[3];
    const float* gatW  = (const float*)d_in[4];
    const float* att_s = (const float*)d_in[5];
    const float* att_d = (const float*)d_in[6];
    const float* gatB  = (const float*)d_in[7];
    const float* mlpW  = (const float*)d_in[8];
    const float* mlpB  = (const float*)d_in[9];
    const float* outW  = (const float*)d_in[10];
    const float* outB  = (const float*)d_in[11];
    float* out = (float*)d_out;

    static cudaStream_t s2 = nullptr;
    static cudaEvent_t evRoot, evConvU, evRed1, evRed2, evNB1, evSort, evS2;
    if (!s2) {
        cudaStreamCreateWithFlags(&s2, cudaStreamNonBlocking);
        cudaEventCreateWithFlags(&evRoot, cudaEventDisableTiming);
        cudaEventCreateWithFlags(&evConvU, cudaEventDisableTiming);
        cudaEventCreateWithFlags(&evRed1, cudaEventDisableTiming);
        cudaEventCreateWithFlags(&evRed2, cudaEventDisableTiming);
        cudaEventCreateWithFlags(&evNB1, cudaEventDisableTiming);
        cudaEventCreateWithFlags(&evSort, cudaEventDisableTiming);
        cudaEventCreateWithFlags(&evS2, cudaEventDisableTiming);
    }

    cudaFuncSetAttribute((const void*)k_mma<1, true, false>, cudaFuncAttributeMaxDynamicSharedMemorySize, smemBytes(1, false));
    cudaFuncSetAttribute((const void*)k_mma<3, true, false>, cudaFuncAttributeMaxDynamicSharedMemorySize, smemBytes(3, false));
    cudaFuncSetAttribute((const void*)k_mma<4, false, true>, cudaFuncAttributeMaxDynamicSharedMemorySize, smemBytes(4, true));
    cudaFuncSetAttribute((const void*)k_mma<1, false, true>, cudaFuncAttributeMaxDynamicSharedMemorySize, smemBytes(1, true));
    cudaFuncSetAttribute((const void*)k_mma<1, true, false>, cudaFuncAttributePreferredSharedMemoryCarveout, 100);
    cudaFuncSetAttribute((const void*)k_mma<3, true, false>, cudaFuncAttributePreferredSharedMemoryCarveout, 100);
    cudaFuncSetAttribute((const void*)k_mma<4, false, true>, cudaFuncAttributePreferredSharedMemoryCarveout, 100);
    cudaFuncSetAttribute((const void*)k_mma<1, false, true>, cudaFuncAttributePreferredSharedMemoryCarveout, 100);

    // ---- fork side stream: convU + CSR ----
    cudaEventRecord(evRoot, 0);
    cudaStreamWaitEvent(s2, evRoot, 0);

    k_convU<<<(int)((KNN / 4 + 255) / 256), 256, 0, s2>>>(U);
    cudaEventRecord(evConvU, s2);
    k_zero<<<16, 256, 0, s2>>>();
    k_hist<<<KE / 256, 256, 0, s2>>>(ei);
    k_scan<<<1, 1024, 0, s2>>>();
    k_fill<<<KE / 256, 256, 0, s2>>>(ei);
    k_sort<<<16, 256, 0, s2>>>(ei);
    cudaEventRecord(evSort, s2);

    // ---- main chain: psi passes ----
    k_absT2<<<32, 256>>>(x);
    k_mma<1, true, false><<<dim3(32, 3, 3), 256, smemBytes(1, false)>>>(0, U, psi, 0); // L1
    k_redT<<<dim3(64, 3), 256>>>(3 * KNF, 1);                                          // -> B 1..3
    cudaEventRecord(evRed1, 0);
    k_mma<3, true, false><<<dim3(32, 3, 3), 256, smemBytes(3, false)>>>(1, U, psi, 0); // L2
    k_redT<<<dim3(64, 9), 256>>>(9 * KNF, 4);                                          // -> B 4..12
    cudaEventRecord(evRed2, 0);

    // ---- s2: coef 0..3 overlaps mode1 (disjoint partial region!); coef 12;
    //          then hes+gatmlp for branches 0..3 ----
    cudaStreamWaitEvent(s2, evRed1, 0);
    k_mma<4, false, true><<<dim3(32, 1, 3), 256, smemBytes(4, true), s2>>>(2, U, psi, 0); // coef 0..3
    cudaStreamWaitEvent(s2, evRed2, 0);
    k_mma<1, false, true><<<dim3(32, 1, 3), 256, smemBytes(1, true), s2>>>(2, U, psi, 0); // coef 12
    cudaEventRecord(evNB1, s2);
    k_hes<<<dim3(64, 4), 256, 0, s2>>>(gatW, att_s, att_d, 0);                            // hes b0..3
    k_gatmlp<<<dim3(KN / 32, 4), 256, 0, s2>>>(gatB, mlpW, mlpB, 0);                      // gat b0..3
    cudaEventRecord(evS2, s2);

    // ---- main: coef 4..11; hes + gatmlp for branches 4..12 ----
    cudaStreamWaitEvent(0, evConvU, 0);
    k_mma<4, false, true><<<dim3(32, 2, 3), 256, smemBytes(4, true)>>>(2, U, psi, 1);     // coef 4..11
    cudaStreamWaitEvent(0, evNB1, 0);
    k_hes<<<dim3(64, 9), 256>>>(gatW, att_s, att_d, 4);                                   // hes b4..12
    cudaStreamWaitEvent(0, evSort, 0);
    k_gatmlp<<<dim3(KN / 32, 9), 256>>>(gatB, mlpW, mlpB, 4);                             // gat b4..12

    // ---- join + final ----
    cudaStreamWaitEvent(0, evS2, 0);
    k_final<<<KN / 8, 256>>>(outW, outB, out);
}